// round 4
// baseline (speedup 1.0000x reference)
#include <cuda_runtime.h>
#include <math.h>

#define N_NODES 50000
#define E_EDGES 800000
#define G_GRAPHS 512
#define HID 64
#define DOUT 128
#define LAYERS 3
#define NEG_SLOPE 0.2f
#define BN_EPS 1e-5f

// ---------------- scratch (device globals; no allocation allowed) ----------------
__device__ float g_h  [N_NODES * HID];
__device__ float g_xl [N_NODES * HID];
__device__ float g_xr [N_NODES * HID];
__device__ int   g_hist[N_NODES];
__device__ int   g_off [N_NODES + 1];
__device__ int   g_cursor[N_NODES];
__device__ int   g_srcS[E_EDGES];
__device__ int   g_dstS[E_EDGES];
__device__ float g_eaS [E_EDGES * 16];
__device__ float g_w   [E_EDGES];
__device__ float g_cnt [G_GRAPHS];

// ---------------- embedding GEMM (also zeroes histogram for CSR build) ----------
__global__ void gemm_emb(const float* __restrict__ A, const float* __restrict__ W,
                         const float* __restrict__ bias) {
    __shared__ float Ws[64][68];
    __shared__ float As[64][68];
    int t = threadIdx.x;           // 256 threads
    int row0 = blockIdx.x * 64;

    int gid = blockIdx.x * 256 + t;
    if (gid < N_NODES) g_hist[gid] = 0;   // piggyback: zero histogram

    #pragma unroll
    for (int i = t; i < 4096; i += 256) { int c = i >> 6, k = i & 63; Ws[c][k] = W[i]; }
    #pragma unroll
    for (int i = t; i < 4096; i += 256) {
        int r = i >> 6, k = i & 63; int gr = row0 + r;
        As[r][k] = (gr < N_NODES) ? A[gr * 64 + k] : 0.f;
    }
    __syncthreads();

    int c  = t & 63;
    int rb = t >> 6;
    float acc[16];
    #pragma unroll
    for (int r = 0; r < 16; r++) acc[r] = 0.f;

    #pragma unroll
    for (int k4 = 0; k4 < 16; k4++) {
        float4 w4 = *(const float4*)&Ws[c][k4 * 4];
        #pragma unroll
        for (int r = 0; r < 16; r++) {
            float4 a4 = *(const float4*)&As[rb * 16 + r][k4 * 4];
            acc[r] += w4.x * a4.x + w4.y * a4.y + w4.z * a4.z + w4.w * a4.w;
        }
    }
    float bb = bias[c];
    #pragma unroll
    for (int r = 0; r < 16; r++) {
        int gr = row0 + rb * 16 + r;
        if (gr < N_NODES) g_h[gr * 64 + c] = acc[r] + bb;
    }
}

// ---------------- CSR build ----------------
__global__ void hist_count(const int* __restrict__ ei) {
    int e = blockIdx.x * blockDim.x + threadIdx.x;
    if (e < E_EDGES) atomicAdd(&g_hist[ei[E_EDGES + e]], 1);
}

__global__ void scan_hist() {      // single block, 1024 threads
    __shared__ int sp[1024];
    const int CH = 49;             // 1024*49 = 50176 >= 50000
    int t = threadIdx.x;
    int base = t * CH;
    int sum = 0;
    for (int i = 0; i < CH; i++) {
        int idx = base + i;
        if (idx < N_NODES) sum += g_hist[idx];
    }
    sp[t] = sum;
    __syncthreads();
    for (int off = 1; off < 1024; off <<= 1) {
        int v = (t >= off) ? sp[t - off] : 0;
        __syncthreads();
        sp[t] += v;
        __syncthreads();
    }
    int run = (t == 0) ? 0 : sp[t - 1];
    for (int i = 0; i < CH; i++) {
        int idx = base + i;
        if (idx < N_NODES) {
            g_off[idx] = run;
            g_cursor[idx] = run;
            run += g_hist[idx];
        }
    }
    if (t == 1023) g_off[N_NODES] = sp[1023];
}

__global__ void scatter_edges(const int* __restrict__ ei, const float* __restrict__ eattr) {
    int e = blockIdx.x * blockDim.x + threadIdx.x;
    if (e >= E_EDGES) return;
    int src = ei[e];
    int dst = ei[E_EDGES + e];
    int pos = atomicAdd(&g_cursor[dst], 1);
    g_srcS[pos] = src;
    g_dstS[pos] = dst;
    const float4* s4 = (const float4*)(eattr + (size_t)e * 16);
    float4* d4 = (float4*)(g_eaS + (size_t)pos * 16);
    d4[0] = s4[0]; d4[1] = s4[1]; d4[2] = s4[2]; d4[3] = s4[3];
}

// ---------------- fused xl/xr GEMM (transposed W in smem: conflict-free) --------
__global__ void gemm_xlxr(const float* __restrict__ Wl, const float* __restrict__ bl,
                          const float* __restrict__ Wr, const float* __restrict__ br) {
    __shared__ float sWlT[64][64];   // [k][c]
    __shared__ float sWrT[64][64];
    __shared__ float sA[32][64];
    int t = threadIdx.x;             // 256
    int row0 = blockIdx.x * 32;

    #pragma unroll
    for (int i = t; i < 4096; i += 256) {
        int c = i >> 6, k = i & 63;
        sWlT[k][c] = Wl[i];
        sWrT[k][c] = Wr[i];
    }
    #pragma unroll
    for (int i = t; i < 2048; i += 256) {
        int r = i >> 6, k = i & 63; int gr = row0 + r;
        sA[r][k] = (gr < N_NODES) ? g_h[gr * 64 + k] : 0.f;
    }
    __syncthreads();

    int c  = t & 63;
    int rb = t >> 6;                 // 0..3, rows rb*8 .. rb*8+7
    float accL[8], accR[8];
    #pragma unroll
    for (int r = 0; r < 8; r++) { accL[r] = 0.f; accR[r] = 0.f; }

    #pragma unroll
    for (int k4 = 0; k4 < 16; k4++) {
        float wl_[4], wr_[4];
        #pragma unroll
        for (int q = 0; q < 4; q++) { wl_[q] = sWlT[k4 * 4 + q][c]; wr_[q] = sWrT[k4 * 4 + q][c]; }
        #pragma unroll
        for (int r = 0; r < 8; r++) {
            float4 a = *(const float4*)&sA[rb * 8 + r][k4 * 4];
            accL[r] += wl_[0] * a.x + wl_[1] * a.y + wl_[2] * a.z + wl_[3] * a.w;
            accR[r] += wr_[0] * a.x + wr_[1] * a.y + wr_[2] * a.z + wr_[3] * a.w;
        }
    }
    float bll = bl[c], brr = br[c];
    #pragma unroll
    for (int r = 0; r < 8; r++) {
        int gr = row0 + rb * 8 + r;
        if (gr < N_NODES) {
            g_xl[gr * 64 + c] = accL[r] + bll;
            g_xr[gr * 64 + c] = accR[r] + brr;
        }
    }
}

// ---------------- edge weights: one warp per edge, no serial loop ----------------
__global__ void edge_w(const float* __restrict__ We, const float* __restrict__ att) {
    __shared__ float sWeT[16][64];   // [k][c] = We[c*16+k]
    __shared__ float satt[64];
    int t = threadIdx.x;             // 256
    #pragma unroll
    for (int i = t; i < 1024; i += 256) {
        int c = i >> 4, k = i & 15;
        sWeT[k][c] = We[i];
    }
    if (t < 64) satt[t] = att[t];
    __syncthreads();

    int e = (blockIdx.x << 3) + (t >> 5);  // 8 warps/block
    if (e >= E_EDGES) return;
    int lane = t & 31;
    int c0 = lane * 2;

    int s = g_srcS[e];
    int d = g_dstS[e];

    float2 vl = *(const float2*)&g_xl[s * 64 + c0];
    float2 vr = *(const float2*)&g_xr[d * 64 + c0];

    const float4* ea4 = (const float4*)(g_eaS + (size_t)e * 16);
    float4 a0 = ea4[0], a1 = ea4[1], a2 = ea4[2], a3 = ea4[3];
    float ar[16] = {a0.x, a0.y, a0.z, a0.w, a1.x, a1.y, a1.z, a1.w,
                    a2.x, a2.y, a2.z, a2.w, a3.x, a3.y, a3.z, a3.w};

    float m0 = vl.x + vr.x;
    float m1 = vl.y + vr.y;
    #pragma unroll
    for (int k = 0; k < 16; k++) {
        float2 wv = *(const float2*)&sWeT[k][c0];
        m0 = fmaf(wv.x, ar[k], m0);
        m1 = fmaf(wv.y, ar[k], m1);
    }
    m0 = fmaxf(m0, NEG_SLOPE * m0);
    m1 = fmaxf(m1, NEG_SLOPE * m1);

    float p = m0 * satt[c0] + m1 * satt[c0 + 1];
    #pragma unroll
    for (int o = 16; o; o >>= 1) p += __shfl_xor_sync(0xffffffffu, p, o);

    if (lane == 0) g_w[e] = __expf(p);   // logits are small; stable without segment-max
}

// ---------------- aggregation: warp per node, light loop, fused epilogue --------
__global__ void gat_agg(const float* __restrict__ cb, const float* __restrict__ gamma,
                        const float* __restrict__ beta, const float* __restrict__ mean,
                        const float* __restrict__ var) {
    int nid = (blockIdx.x * blockDim.x + threadIdx.x) >> 5;
    if (nid >= N_NODES) return;
    int lane = threadIdx.x & 31;
    int c0 = lane * 2;

    int jb = g_off[nid], je = g_off[nid + 1];

    float acc0 = 0.f, acc1 = 0.f, accd = 0.f;
    int j = jb;
    // 4-way unrolled main loop for MLP
    for (; j + 4 <= je; j += 4) {
        float w0 = __ldg(&g_w[j]),     w1 = __ldg(&g_w[j + 1]);
        float w2 = __ldg(&g_w[j + 2]), w3 = __ldg(&g_w[j + 3]);
        int s0 = __ldg(&g_srcS[j]),     s1 = __ldg(&g_srcS[j + 1]);
        int s2 = __ldg(&g_srcS[j + 2]), s3 = __ldg(&g_srcS[j + 3]);
        float2 v0 = *(const float2*)&g_xl[s0 * 64 + c0];
        float2 v1 = *(const float2*)&g_xl[s1 * 64 + c0];
        float2 v2 = *(const float2*)&g_xl[s2 * 64 + c0];
        float2 v3 = *(const float2*)&g_xl[s3 * 64 + c0];
        accd += (w0 + w1) + (w2 + w3);
        acc0 = fmaf(w0, v0.x, acc0); acc1 = fmaf(w0, v0.y, acc1);
        acc0 = fmaf(w1, v1.x, acc0); acc1 = fmaf(w1, v1.y, acc1);
        acc0 = fmaf(w2, v2.x, acc0); acc1 = fmaf(w2, v2.y, acc1);
        acc0 = fmaf(w3, v3.x, acc0); acc1 = fmaf(w3, v3.y, acc1);
    }
    for (; j < je; j++) {
        float w = __ldg(&g_w[j]);
        int s = __ldg(&g_srcS[j]);
        float2 v = *(const float2*)&g_xl[s * 64 + c0];
        accd += w;
        acc0 = fmaf(w, v.x, acc0);
        acc1 = fmaf(w, v.y, acc1);
    }

    float inv = 1.f / (accd + 1e-16f);
    float o0 = acc0 * inv + __ldg(&cb[c0]);
    float o1 = acc1 * inv + __ldg(&cb[c0 + 1]);
    o0 = (o0 - __ldg(&mean[c0]))     * rsqrtf(__ldg(&var[c0])     + BN_EPS) * __ldg(&gamma[c0])     + __ldg(&beta[c0]);
    o1 = (o1 - __ldg(&mean[c0 + 1])) * rsqrtf(__ldg(&var[c0 + 1]) + BN_EPS) * __ldg(&gamma[c0 + 1]) + __ldg(&beta[c0 + 1]);
    o0 = 0.5f * o0 * (1.f + erff(o0 * 0.70710678118654752f));
    o1 = 0.5f * o1 * (1.f + erff(o1 * 0.70710678118654752f));

    float2 h = *(float2*)&g_h[nid * 64 + c0];
    h.x += o0; h.y += o1;
    *(float2*)&g_h[nid * 64 + c0] = h;
}

// ---------------- pooling ----------------
__global__ void init_pool(float* __restrict__ out) {
    int idx = blockIdx.x * blockDim.x + threadIdx.x;
    if (idx < G_GRAPHS * DOUT) out[idx] = 0.f;
    if (idx < G_GRAPHS) g_cnt[idx] = 0.f;
}

__global__ void count_nodes(const int* __restrict__ batch) {
    int n = blockIdx.x * blockDim.x + threadIdx.x;
    if (n < N_NODES) atomicAdd(&g_cnt[batch[n]], 1.f);
}

__global__ void lin_pool(const float* __restrict__ W, const float* __restrict__ bias,
                         const int* __restrict__ batch, float* __restrict__ pooled) {
    __shared__ float Ws[128][68];
    __shared__ float As[32][68];
    int t = threadIdx.x;            // 256
    int row0 = blockIdx.x * 32;

    for (int i = t; i < 128 * 64; i += 256) { int c = i >> 6, k = i & 63; Ws[c][k] = W[i]; }
    for (int i = t; i < 32 * 64; i += 256) {
        int r = i >> 6, k = i & 63; int gr = row0 + r;
        As[r][k] = (gr < N_NODES) ? g_h[gr * 64 + k] : 0.f;
    }
    __syncthreads();

    int c  = t & 127;
    int rb = t >> 7;
    float acc[16];
    #pragma unroll
    for (int r = 0; r < 16; r++) acc[r] = 0.f;

    #pragma unroll
    for (int k4 = 0; k4 < 16; k4++) {
        float4 w4 = *(const float4*)&Ws[c][k4 * 4];
        #pragma unroll
        for (int r = 0; r < 16; r++) {
            float4 a4 = *(const float4*)&As[rb * 16 + r][k4 * 4];
            acc[r] += w4.x * a4.x + w4.y * a4.y + w4.z * a4.z + w4.w * a4.w;
        }
    }
    float bb = bias[c];
    #pragma unroll
    for (int r = 0; r < 16; r++) {
        int gr = row0 + rb * 16 + r;
        if (gr < N_NODES)
            atomicAdd(&pooled[batch[gr] * DOUT + c], acc[r] + bb);
    }
}

__global__ void finalize(float* __restrict__ out) {
    int idx = blockIdx.x * blockDim.x + threadIdx.x;
    if (idx >= G_GRAPHS * DOUT) return;
    out[idx] /= fmaxf(g_cnt[idx >> 7], 1.f);
}

// ---------------- launch ----------------
extern "C" void kernel_launch(void* const* d_in, const int* in_sizes, int n_in,
                              void* d_out, int out_size) {
    const float* x         = (const float*)d_in[0];
    const int*   ei        = (const int*)  d_in[1];
    const float* eattr     = (const float*)d_in[2];
    const int*   batch     = (const int*)  d_in[3];
    const float* emb_W     = (const float*)d_in[4];
    const float* emb_b     = (const float*)d_in[5];
    const float* Wl        = (const float*)d_in[6];
    const float* bl        = (const float*)d_in[7];
    const float* Wr        = (const float*)d_in[8];
    const float* br        = (const float*)d_in[9];
    const float* We        = (const float*)d_in[10];
    const float* att       = (const float*)d_in[11];
    const float* conv_bias = (const float*)d_in[12];
    const float* gamma     = (const float*)d_in[13];
    const float* beta      = (const float*)d_in[14];
    const float* mean      = (const float*)d_in[15];
    const float* var       = (const float*)d_in[16];
    const float* lin_W     = (const float*)d_in[17];
    const float* lin_b     = (const float*)d_in[18];
    float* out = (float*)d_out;

    const int EMB_BLOCKS  = (N_NODES + 63) / 64;            // 782
    const int XLR_BLOCKS  = (N_NODES + 31) / 32;            // 1563
    const int EDGE_BLOCKS = (E_EDGES + 255) / 256;          // 3125
    const int EW_BLOCKS   = (E_EDGES + 7) / 8;              // 100000 (warp/edge)
    const int AGG_BLOCKS  = (N_NODES * 32 + 255) / 256;     // 6250

    gemm_emb<<<EMB_BLOCKS, 256>>>(x, emb_W, emb_b);
    hist_count<<<EDGE_BLOCKS, 256>>>(ei);
    scan_hist<<<1, 1024>>>();
    scatter_edges<<<EDGE_BLOCKS, 256>>>(ei, eattr);

    for (int l = 0; l < LAYERS; l++) {
        gemm_xlxr<<<XLR_BLOCKS, 256>>>(Wl + l * 4096, bl + l * 64, Wr + l * 4096, br + l * 64);
        edge_w<<<EW_BLOCKS, 256>>>(We + l * 1024, att + l * 64);
        gat_agg<<<AGG_BLOCKS, 256>>>(conv_bias + l * 64, gamma + l * 64, beta + l * 64,
                                     mean + l * 64, var + l * 64);
    }

    init_pool<<<(G_GRAPHS * DOUT + 255) / 256, 256>>>(out);
    count_nodes<<<(N_NODES + 255) / 256, 256>>>(batch);
    lin_pool<<<(N_NODES + 31) / 32, 256>>>(lin_W, lin_b, batch, out);
    finalize<<<(G_GRAPHS * DOUT + 255) / 256, 256>>>(out);
}

// round 5
// speedup vs baseline: 1.7565x; 1.7565x over previous
#include <cuda_runtime.h>
#include <math.h>

#define N_NODES 50000
#define E_EDGES 800000
#define G_GRAPHS 512
#define HID 64
#define DOUT 128
#define LAYERS 3
#define NEG_SLOPE 0.2f
#define BN_EPS 1e-5f

// ---------------- scratch (device globals; no allocation allowed) ----------------
__device__ float g_h  [N_NODES * HID];
__device__ float g_xl [N_NODES * HID];
__device__ float g_xr [N_NODES * HID];
__device__ int   g_hist[N_NODES];
__device__ int   g_off [N_NODES + 1];
__device__ int   g_cursor[N_NODES];
__device__ int   g_srcS[E_EDGES];
__device__ float g_eaS [E_EDGES * 16];
__device__ float g_cnt [G_GRAPHS];

// ---------------- embedding GEMM (also zeroes histogram for CSR build) ----------
__global__ void gemm_emb(const float* __restrict__ A, const float* __restrict__ W,
                         const float* __restrict__ bias) {
    __shared__ float Ws[64][68];
    __shared__ float As[64][68];
    int t = threadIdx.x;           // 256 threads
    int row0 = blockIdx.x * 64;

    int gid = blockIdx.x * 256 + t;
    if (gid < N_NODES) g_hist[gid] = 0;   // piggyback: zero histogram

    #pragma unroll
    for (int i = t; i < 4096; i += 256) { int c = i >> 6, k = i & 63; Ws[c][k] = W[i]; }
    #pragma unroll
    for (int i = t; i < 4096; i += 256) {
        int r = i >> 6, k = i & 63; int gr = row0 + r;
        As[r][k] = (gr < N_NODES) ? A[gr * 64 + k] : 0.f;
    }
    __syncthreads();

    int c  = t & 63;
    int rb = t >> 6;
    float acc[16];
    #pragma unroll
    for (int r = 0; r < 16; r++) acc[r] = 0.f;

    #pragma unroll
    for (int k4 = 0; k4 < 16; k4++) {
        float4 w4 = *(const float4*)&Ws[c][k4 * 4];
        #pragma unroll
        for (int r = 0; r < 16; r++) {
            float4 a4 = *(const float4*)&As[rb * 16 + r][k4 * 4];
            acc[r] += w4.x * a4.x + w4.y * a4.y + w4.z * a4.z + w4.w * a4.w;
        }
    }
    float bb = bias[c];
    #pragma unroll
    for (int r = 0; r < 16; r++) {
        int gr = row0 + rb * 16 + r;
        if (gr < N_NODES) g_h[gr * 64 + c] = acc[r] + bb;
    }
}

// ---------------- CSR build ----------------
__global__ void hist_count(const int* __restrict__ ei) {
    int e = blockIdx.x * blockDim.x + threadIdx.x;
    if (e < E_EDGES) atomicAdd(&g_hist[ei[E_EDGES + e]], 1);
}

__global__ void scan_hist() {      // single block, 1024 threads
    __shared__ int sp[1024];
    const int CH = 49;             // 1024*49 = 50176 >= 50000
    int t = threadIdx.x;
    int base = t * CH;
    int sum = 0;
    for (int i = 0; i < CH; i++) {
        int idx = base + i;
        if (idx < N_NODES) sum += g_hist[idx];
    }
    sp[t] = sum;
    __syncthreads();
    for (int off = 1; off < 1024; off <<= 1) {
        int v = (t >= off) ? sp[t - off] : 0;
        __syncthreads();
        sp[t] += v;
        __syncthreads();
    }
    int run = (t == 0) ? 0 : sp[t - 1];
    for (int i = 0; i < CH; i++) {
        int idx = base + i;
        if (idx < N_NODES) {
            g_off[idx] = run;
            g_cursor[idx] = run;
            run += g_hist[idx];
        }
    }
    if (t == 1023) g_off[N_NODES] = sp[1023];
}

__global__ void scatter_edges(const int* __restrict__ ei, const float* __restrict__ eattr) {
    int e = blockIdx.x * blockDim.x + threadIdx.x;
    if (e >= E_EDGES) return;
    int src = ei[e];
    int dst = ei[E_EDGES + e];
    int pos = atomicAdd(&g_cursor[dst], 1);
    g_srcS[pos] = src;
    const float4* s4 = (const float4*)(eattr + (size_t)e * 16);
    float4* d4 = (float4*)(g_eaS + (size_t)pos * 16);
    d4[0] = s4[0]; d4[1] = s4[1]; d4[2] = s4[2]; d4[3] = s4[3];
}

// ---------------- fused xl/xr GEMM (transposed W in smem: conflict-free) --------
__global__ void gemm_xlxr(const float* __restrict__ Wl, const float* __restrict__ bl,
                          const float* __restrict__ Wr, const float* __restrict__ br) {
    __shared__ float sWlT[64][64];   // [k][c]
    __shared__ float sWrT[64][64];
    __shared__ float sA[32][64];
    int t = threadIdx.x;             // 256
    int row0 = blockIdx.x * 32;

    #pragma unroll
    for (int i = t; i < 4096; i += 256) {
        int c = i >> 6, k = i & 63;
        sWlT[k][c] = Wl[i];
        sWrT[k][c] = Wr[i];
    }
    #pragma unroll
    for (int i = t; i < 2048; i += 256) {
        int r = i >> 6, k = i & 63; int gr = row0 + r;
        sA[r][k] = (gr < N_NODES) ? g_h[gr * 64 + k] : 0.f;
    }
    __syncthreads();

    int c  = t & 63;
    int rb = t >> 6;                 // 0..3, rows rb*8 .. rb*8+7
    float accL[8], accR[8];
    #pragma unroll
    for (int r = 0; r < 8; r++) { accL[r] = 0.f; accR[r] = 0.f; }

    #pragma unroll
    for (int k4 = 0; k4 < 16; k4++) {
        float wl_[4], wr_[4];
        #pragma unroll
        for (int q = 0; q < 4; q++) { wl_[q] = sWlT[k4 * 4 + q][c]; wr_[q] = sWrT[k4 * 4 + q][c]; }
        #pragma unroll
        for (int r = 0; r < 8; r++) {
            float4 a = *(const float4*)&sA[rb * 8 + r][k4 * 4];
            accL[r] += wl_[0] * a.x + wl_[1] * a.y + wl_[2] * a.z + wl_[3] * a.w;
            accR[r] += wr_[0] * a.x + wr_[1] * a.y + wr_[2] * a.z + wr_[3] * a.w;
        }
    }
    float bll = bl[c], brr = br[c];
    #pragma unroll
    for (int r = 0; r < 8; r++) {
        int gr = row0 + rb * 8 + r;
        if (gr < N_NODES) {
            g_xl[gr * 64 + c] = accL[r] + bll;
            g_xr[gr * 64 + c] = accR[r] + brr;
        }
    }
}

// ---- fused GAT layer: warp per node, HALF-WARP per edge (2 edges/iteration) ----
// lane owns 4 channels (cg = lane&15); We in smem; zero atomics; fused epilogue.
__global__ void gat_layer(const float* __restrict__ We, const float* __restrict__ att,
                          const float* __restrict__ cb, const float* __restrict__ gamma,
                          const float* __restrict__ beta, const float* __restrict__ mean,
                          const float* __restrict__ var) {
    __shared__ float4 sWe[16][16];   // sWe[k][cg] = We rows cg*4..cg*4+3 at col k
    int t = threadIdx.x;             // 256 threads = 8 warps = 8 nodes
    if (t < 256) {
        int k = t >> 4, cg = t & 15;
        sWe[k][cg] = make_float4(We[(cg * 4 + 0) * 16 + k], We[(cg * 4 + 1) * 16 + k],
                                 We[(cg * 4 + 2) * 16 + k], We[(cg * 4 + 3) * 16 + k]);
    }
    __syncthreads();

    int nid = (blockIdx.x * blockDim.x + t) >> 5;   // grid sized exactly: 6250*8 = 50000
    int lane = t & 31;
    int half = lane >> 4;            // 0 or 1: which edge of the pair
    int cg   = lane & 15;            // channel group: channels cg*4 .. cg*4+3

    float4 vr = *(const float4*)&g_xr[nid * 64 + cg * 4];
    float4 a4 = __ldg((const float4*)att + cg);

    int jb = g_off[nid], je = g_off[nid + 1];

    float4 acc = make_float4(0.f, 0.f, 0.f, 0.f);
    float accd = 0.f;

    for (int j0 = jb; j0 < je; j0 += 2) {
        int j = j0 + half;
        bool valid = (j < je);
        int jc = valid ? j : jb;                 // safe dummy index
        int s = __ldg(&g_srcS[jc]);
        float4 vl = *(const float4*)&g_xl[s * 64 + cg * 4];
        const float4* ea4 = (const float4*)(g_eaS + (size_t)jc * 16);
        float4 e0 = ea4[0], e1 = ea4[1], e2 = ea4[2], e3 = ea4[3];
        float ar[16] = {e0.x, e0.y, e0.z, e0.w, e1.x, e1.y, e1.z, e1.w,
                        e2.x, e2.y, e2.z, e2.w, e3.x, e3.y, e3.z, e3.w};

        float m0 = vl.x + vr.x, m1 = vl.y + vr.y, m2 = vl.z + vr.z, m3 = vl.w + vr.w;
        #pragma unroll
        for (int k = 0; k < 16; k++) {
            float4 wv = sWe[k][cg];
            m0 = fmaf(wv.x, ar[k], m0);
            m1 = fmaf(wv.y, ar[k], m1);
            m2 = fmaf(wv.z, ar[k], m2);
            m3 = fmaf(wv.w, ar[k], m3);
        }
        m0 = fmaxf(m0, NEG_SLOPE * m0);
        m1 = fmaxf(m1, NEG_SLOPE * m1);
        m2 = fmaxf(m2, NEG_SLOPE * m2);
        m3 = fmaxf(m3, NEG_SLOPE * m3);

        float p = m0 * a4.x + m1 * a4.y + m2 * a4.z + m3 * a4.w;
        #pragma unroll
        for (int o = 1; o <= 8; o <<= 1) p += __shfl_xor_sync(0xffffffffu, p, o);

        float w = valid ? __expf(p) : 0.f;       // logits small; stable without segment-max
        accd += w;
        acc.x = fmaf(w, vl.x, acc.x);
        acc.y = fmaf(w, vl.y, acc.y);
        acc.z = fmaf(w, vl.z, acc.z);
        acc.w = fmaf(w, vl.w, acc.w);
    }

    // merge the two half-warp accumulators
    acc.x += __shfl_xor_sync(0xffffffffu, acc.x, 16);
    acc.y += __shfl_xor_sync(0xffffffffu, acc.y, 16);
    acc.z += __shfl_xor_sync(0xffffffffu, acc.z, 16);
    acc.w += __shfl_xor_sync(0xffffffffu, acc.w, 16);
    accd  += __shfl_xor_sync(0xffffffffu, accd, 16);

    if (half == 0) {
        float inv = 1.f / (accd + 1e-16f);
        float4 b4  = __ldg((const float4*)cb + cg);
        float4 mu4 = __ldg((const float4*)mean + cg);
        float4 v4  = __ldg((const float4*)var + cg);
        float4 gm4 = __ldg((const float4*)gamma + cg);
        float4 bt4 = __ldg((const float4*)beta + cg);
        float o[4] = {acc.x * inv + b4.x, acc.y * inv + b4.y,
                      acc.z * inv + b4.z, acc.w * inv + b4.w};
        float mu[4] = {mu4.x, mu4.y, mu4.z, mu4.w};
        float vv[4] = {v4.x, v4.y, v4.z, v4.w};
        float gm[4] = {gm4.x, gm4.y, gm4.z, gm4.w};
        float bt[4] = {bt4.x, bt4.y, bt4.z, bt4.w};
        #pragma unroll
        for (int q = 0; q < 4; q++) {
            float z = (o[q] - mu[q]) * rsqrtf(vv[q] + BN_EPS) * gm[q] + bt[q];
            o[q] = 0.5f * z * (1.f + erff(z * 0.70710678118654752f));
        }
        float4 h = *(float4*)&g_h[nid * 64 + cg * 4];
        h.x += o[0]; h.y += o[1]; h.z += o[2]; h.w += o[3];
        *(float4*)&g_h[nid * 64 + cg * 4] = h;
    }
}

// ---------------- pooling ----------------
__global__ void init_pool(float* __restrict__ out) {
    int idx = blockIdx.x * blockDim.x + threadIdx.x;
    if (idx < G_GRAPHS * DOUT) out[idx] = 0.f;
    if (idx < G_GRAPHS) g_cnt[idx] = 0.f;
}

__global__ void count_nodes(const int* __restrict__ batch) {
    int n = blockIdx.x * blockDim.x + threadIdx.x;
    if (n < N_NODES) atomicAdd(&g_cnt[batch[n]], 1.f);
}

__global__ void lin_pool(const float* __restrict__ W, const float* __restrict__ bias,
                         const int* __restrict__ batch, float* __restrict__ pooled) {
    __shared__ float Ws[128][68];
    __shared__ float As[32][68];
    int t = threadIdx.x;            // 256
    int row0 = blockIdx.x * 32;

    for (int i = t; i < 128 * 64; i += 256) { int c = i >> 6, k = i & 63; Ws[c][k] = W[i]; }
    for (int i = t; i < 32 * 64; i += 256) {
        int r = i >> 6, k = i & 63; int gr = row0 + r;
        As[r][k] = (gr < N_NODES) ? g_h[gr * 64 + k] : 0.f;
    }
    __syncthreads();

    int c  = t & 127;
    int rb = t >> 7;
    float acc[16];
    #pragma unroll
    for (int r = 0; r < 16; r++) acc[r] = 0.f;

    #pragma unroll
    for (int k4 = 0; k4 < 16; k4++) {
        float4 w4 = *(const float4*)&Ws[c][k4 * 4];
        #pragma unroll
        for (int r = 0; r < 16; r++) {
            float4 a4 = *(const float4*)&As[rb * 16 + r][k4 * 4];
            acc[r] += w4.x * a4.x + w4.y * a4.y + w4.z * a4.z + w4.w * a4.w;
        }
    }
    float bb = bias[c];
    #pragma unroll
    for (int r = 0; r < 16; r++) {
        int gr = row0 + rb * 16 + r;
        if (gr < N_NODES)
            atomicAdd(&pooled[batch[gr] * DOUT + c], acc[r] + bb);
    }
}

__global__ void finalize(float* __restrict__ out) {
    int idx = blockIdx.x * blockDim.x + threadIdx.x;
    if (idx >= G_GRAPHS * DOUT) return;
    out[idx] /= fmaxf(g_cnt[idx >> 7], 1.f);
}

// ---------------- launch ----------------
extern "C" void kernel_launch(void* const* d_in, const int* in_sizes, int n_in,
                              void* d_out, int out_size) {
    const float* x         = (const float*)d_in[0];
    const int*   ei        = (const int*)  d_in[1];
    const float* eattr     = (const float*)d_in[2];
    const int*   batch     = (const int*)  d_in[3];
    const float* emb_W     = (const float*)d_in[4];
    const float* emb_b     = (const float*)d_in[5];
    const float* Wl        = (const float*)d_in[6];
    const float* bl        = (const float*)d_in[7];
    const float* Wr        = (const float*)d_in[8];
    const float* br        = (const float*)d_in[9];
    const float* We        = (const float*)d_in[10];
    const float* att       = (const float*)d_in[11];
    const float* conv_bias = (const float*)d_in[12];
    const float* gamma     = (const float*)d_in[13];
    const float* beta      = (const float*)d_in[14];
    const float* mean      = (const float*)d_in[15];
    const float* var       = (const float*)d_in[16];
    const float* lin_W     = (const float*)d_in[17];
    const float* lin_b     = (const float*)d_in[18];
    float* out = (float*)d_out;

    const int EMB_BLOCKS  = (N_NODES + 63) / 64;            // 782
    const int XLR_BLOCKS  = (N_NODES + 31) / 32;            // 1563
    const int EDGE_BLOCKS = (E_EDGES + 255) / 256;          // 3125
    const int GAT_BLOCKS  = N_NODES / 8;                    // 6250 (8 nodes/block, exact)

    gemm_emb<<<EMB_BLOCKS, 256>>>(x, emb_W, emb_b);
    hist_count<<<EDGE_BLOCKS, 256>>>(ei);
    scan_hist<<<1, 1024>>>();
    scatter_edges<<<EDGE_BLOCKS, 256>>>(ei, eattr);

    for (int l = 0; l < LAYERS; l++) {
        gemm_xlxr<<<XLR_BLOCKS, 256>>>(Wl + l * 4096, bl + l * 64, Wr + l * 4096, br + l * 64);
        gat_layer<<<GAT_BLOCKS, 256>>>(We + l * 1024, att + l * 64, conv_bias + l * 64,
                                       gamma + l * 64, beta + l * 64, mean + l * 64, var + l * 64);
    }

    init_pool<<<(G_GRAPHS * DOUT + 255) / 256, 256>>>(out);
    count_nodes<<<(N_NODES + 255) / 256, 256>>>(batch);
    lin_pool<<<(N_NODES + 31) / 32, 256>>>(lin_W, lin_b, batch, out);
    finalize<<<(G_GRAPHS * DOUT + 255) / 256, 256>>>(out);
}